// round 2
// baseline (speedup 1.0000x reference)
#include <cuda_runtime.h>

typedef unsigned long long u64;
typedef unsigned int u32;

#define T_FRAMES 5
#define WS 8
#define HEADS 6
#define DIM 192
#define HDIM 32
#define NTOK 320
#define KROW 36   // padded row (floats) for K/V smem tiles

// scratch: per-window attention output, [wb][n][DIM], sized for B=2
__device__ float g_scratch[2 * 64 * NTOK * DIM];

// ---------------- f32x2 helpers (sm_100+ packed fp32) ----------------
__device__ __forceinline__ u64 pack2(float lo, float hi) {
    u64 r; asm("mov.b64 %0,{%1,%2};" : "=l"(r) : "f"(lo), "f"(hi)); return r;
}
__device__ __forceinline__ void unpack2(u64 v, float &lo, float &hi) {
    asm("mov.b64 {%0,%1},%2;" : "=f"(lo), "=f"(hi) : "l"(v));
}
__device__ __forceinline__ u64 add2(u64 a, u64 b) {
    u64 r; asm("add.rn.f32x2 %0,%1,%2;" : "=l"(r) : "l"(a), "l"(b)); return r;
}
__device__ __forceinline__ void fma2(u64 &d, u64 a, u64 b) {
    asm("fma.rn.f32x2 %0,%1,%2,%0;" : "+l"(d) : "l"(a), "l"(b));
}
// 16B smem load + 2 packed FMAs: d0 += q0*k[0:2], d1 += q1*k[2:4]
__device__ __forceinline__ void dot_frag(u64 &d0, u64 &d1, u64 q0, u64 q1, u32 sa) {
    asm volatile("{\n\t.reg .b64 t0,t1;\n\t"
        "ld.shared.v2.b64 {t0,t1},[%2];\n\t"
        "fma.rn.f32x2 %0,%3,t0,%0;\n\t"
        "fma.rn.f32x2 %1,%4,t1,%1;\n\t}"
        : "+l"(d0), "+l"(d1) : "r"(sa), "l"(q0), "l"(q1));
}
// 16B smem load + 2 packed FMAs with broadcast multiplier pp
__device__ __forceinline__ void av_frag(u64 &a0, u64 &a1, u64 pp, u32 sa) {
    asm volatile("{\n\t.reg .b64 t0,t1;\n\t"
        "ld.shared.v2.b64 {t0,t1},[%2];\n\t"
        "fma.rn.f32x2 %0,t0,%3,%0;\n\t"
        "fma.rn.f32x2 %1,t1,%3,%1;\n\t}"
        : "+l"(a0), "+l"(a1) : "r"(sa), "l"(pp));
}
__device__ __forceinline__ u64 lds64(u32 sa) {
    u64 r; asm volatile("ld.shared.b64 %0,[%1];" : "=l"(r) : "r"(sa)); return r;
}

// ---------------- attention kernel ----------------
// smem layout (floats): K tile | V tile | bias column | token meta
#define SM_V    (NTOK * KROW)
#define SM_BIAS (2 * NTOK * KROW)
#define SM_META (SM_BIAS + 1185)
#define ATTN_SMEM ((SM_META + NTOK) * 4)

__global__ void __launch_bounds__(320, 2)
attn_kernel(const float* __restrict__ qkv, const float* __restrict__ bias_table)
{
    extern __shared__ float sm[];
    float* k_s    = sm;
    float* v_s    = sm + SM_V;
    float* bias_s = sm + SM_BIAS;
    int*   meta_s = (int*)(sm + SM_META);

    const int head = blockIdx.y;
    const int wb   = blockIdx.x;          // b*64 + widx
    const int b    = wb >> 6;
    const int widx = wb & 63;
    const int hw = widx >> 3, ww = widx & 7;

    const int i  = threadIdx.x;           // query token 0..319
    const int t  = i >> 6;
    const int hs = (i >> 3) & 7;
    const int wsv = i & 7;
    const int Hp = hw * 8 + hs;           // shifted-frame coords
    const int Wp = ww * 8 + wsv;
    const int h = (Hp + 4) & 63;          // un-shift: roll(-4) gather
    const int w = (Wp + 4) & 63;
    // Swin shift mask regions (computed, not loaded)
    const int rh = (Hp < 56) ? 0 : ((Hp < 60) ? 1 : 2);
    const int rw = (Wp < 56) ? 0 : ((Wp < 60) ? 1 : 2);
    const int r_i = rh * 3 + rw;
    const int bj  = t * 15 + hs + wsv;    // rel-bias component
    meta_s[i] = bj | (r_i << 8);

    const int row = ((b * T_FRAMES + t) << 12) + (h << 6) + w;
    const float* qp = qkv + (size_t)row * (3 * DIM) + head * HDIM;

    // K, V rows into smem — cooperative, coalesced: 16 consecutive threads
    // stage one token row (8 K float4s + 8 V float4s).
    {
        const int bT = b * T_FRAMES;
        #pragma unroll
        for (int it = 0; it < 16; ++it) {
            const int lin = it * NTOK + i;     // 0..5119
            const int r   = lin >> 4;
            const int g   = lin & 15;
            const int rt  = r >> 6;
            const int rhs = (r >> 3) & 7;
            const int rws = r & 7;
            const int rh_ = (hw * 8 + rhs + 4) & 63;
            const int rw_ = (ww * 8 + rws + 4) & 63;
            const float* rowp = qkv + (size_t)(((bT + rt) << 12) + (rh_ << 6) + rw_) * (3 * DIM)
                                + head * HDIM;
            const int gg = g & 7;
            const float4 val = ((const float4*)(rowp + DIM + ((g >= 8) ? DIM : 0)))[gg];
            float* dst = ((g >= 8) ? v_s : k_s) + r * KROW;
            ((float4*)dst)[gg] = val;
        }
    }
    const float LOG2E = 1.4426950408889634f;
    for (int idx = i; idx < 1185; idx += NTOK)
        bias_s[idx] = bias_table[idx * HEADS + head] * LOG2E;

    // q into registers, pre-scaled by SCALE * log2(e)
    const float qs_f = 0.17677669529663687f * LOG2E;
    u64 q[16];
    {
        const float4* qv = (const float4*)qp;
        #pragma unroll
        for (int m = 0; m < 8; ++m) {
            float4 f = qv[m];
            q[2 * m]     = pack2(f.x * qs_f, f.y * qs_f);
            q[2 * m + 1] = pack2(f.z * qs_f, f.w * qs_f);
        }
    }
    __syncthreads();

    const u32 kbase = (u32)__cvta_generic_to_shared(k_s);
    const u32 vbase = (u32)__cvta_generic_to_shared(v_s);

    u64 acc[16];
    #pragma unroll
    for (int m = 0; m < 16; ++m) acc[m] = 0ULL;
    float l = 0.f;
    const int a_i = bj + 112;

    #pragma unroll 1
    for (int j = 0; j < NTOK; ++j) {
        const int mj = meta_s[j];
        const u32 ka = kbase + j * (KROW * 4);
        u64 d0 = 0, d1 = 0, d2 = 0, d3 = 0;
        dot_frag(d0, d1, q[0],  q[1],  ka);
        dot_frag(d2, d3, q[2],  q[3],  ka + 16);
        dot_frag(d0, d1, q[4],  q[5],  ka + 32);
        dot_frag(d2, d3, q[6],  q[7],  ka + 48);
        dot_frag(d0, d1, q[8],  q[9],  ka + 64);
        dot_frag(d2, d3, q[10], q[11], ka + 80);
        dot_frag(d0, d1, q[12], q[13], ka + 96);
        dot_frag(d2, d3, q[14], q[15], ka + 112);
        u64 e = add2(add2(d0, d1), add2(d2, d3));
        float sx, sy; unpack2(e, sx, sy);
        const float s = sx + sy + bias_s[a_i - (mj & 255)];
        float p; asm("ex2.approx.ftz.f32 %0,%1;" : "=f"(p) : "f"(s));
        p = ((mj >> 8) == r_i) ? p : 0.f;   // mask: exclude cross-region keys
        l += p;
        const u64 pp = pack2(p, p);
        const u32 va = vbase + j * (KROW * 4);
        av_frag(acc[0],  acc[1],  pp, va);
        av_frag(acc[2],  acc[3],  pp, va + 16);
        av_frag(acc[4],  acc[5],  pp, va + 32);
        av_frag(acc[6],  acc[7],  pp, va + 48);
        av_frag(acc[8],  acc[9],  pp, va + 64);
        av_frag(acc[10], acc[11], pp, va + 80);
        av_frag(acc[12], acc[13], pp, va + 96);
        av_frag(acc[14], acc[15], pp, va + 112);
    }

    const float inv = 1.0f / l;
    float4* op = (float4*)(g_scratch + ((size_t)(wb * NTOK + i)) * DIM + head * HDIM);
    #pragma unroll
    for (int m = 0; m < 8; ++m) {
        float x0, x1, x2, x3;
        unpack2(acc[2 * m],     x0, x1);
        unpack2(acc[2 * m + 1], x2, x3);
        op[m] = make_float4(x0 * inv, x1 * inv, x2 * inv, x3 * inv);
    }
}

// ---------------- projection + window-reverse kernel ----------------
// k-tiled W staging: W tile [192 out][66 pad] (k-tile of 64), full o chunk
// [64 tok][196 pad]. smem ~101 KB -> 2 CTAs/SM.
#define KT 64
#define WP 66
#define OP 196
#define PROJ_SMEM ((DIM * WP + 64 * OP) * 4)

__global__ void __launch_bounds__(256, 2)
proj_kernel(const float* __restrict__ pw, const float* __restrict__ pb,
            float* __restrict__ out, int nchunks)
{
    extern __shared__ float sm[];
    float* Wsh = sm;                 // [192][WP]  (c-major rows, k within tile)
    float* o_s = sm + DIM * WP;      // [64][OP]   (full 192-k per token)
    const int tid = threadIdx.x, tx = tid & 31, ty = tid >> 5;

    float pbv[6];
    #pragma unroll
    for (int j = 0; j < 6; ++j) pbv[j] = pb[j * 32 + tx];

    const u32 wbase = (u32)__cvta_generic_to_shared(Wsh) + tx * (WP * 4);
    const u32 obase = (u32)__cvta_generic_to_shared(o_s) + ty * (8 * OP * 4);

    for (int ci = blockIdx.x; ci < nchunks; ci += gridDim.x) {
        __syncthreads();   // previous chunk's compute done before restaging o
        // stage o chunk [64 tokens][192 k]
        const float* src = g_scratch + (size_t)ci * (64 * DIM);  // ci = wb*5 + t
        #pragma unroll
        for (int it = 0; it < 12; ++it) {
            const int idx = tid * 4 + it * 1024;
            float4 v = *(const float4*)(src + idx);
            const int tok = idx / DIM, k = idx - tok * DIM;
            *(float4*)(o_s + tok * OP + k) = v;
        }

        u64 acc[8][6];
        #pragma unroll
        for (int m = 0; m < 8; ++m)
            #pragma unroll
            for (int j = 0; j < 6; ++j) acc[m][j] = 0ULL;

        for (int kt = 0; kt < 3; ++kt) {
            __syncthreads();   // o ready (kt=0) / previous W tile consumed
            // stage W tile: W[c][kt*64 + k2*2 .. +1] -> Wsh[c*WP + k2*2]
            #pragma unroll
            for (int it = 0; it < 24; ++it) {
                const int lin = tid + it * 256;
                const int c = lin >> 5, k2 = lin & 31;
                float2 v = *(const float2*)(pw + c * DIM + kt * KT + k2 * 2);
                *(float2*)(Wsh + c * WP + k2 * 2) = v;
            }
            __syncthreads();

            const int kof = kt * KT;
            #pragma unroll 2
            for (int k = 0; k < KT; k += 2) {
                u64 w2[6], o2[8];
                #pragma unroll
                for (int j = 0; j < 6; ++j)
                    w2[j] = lds64(wbase + (u32)(j * 32 * WP * 4) + k * 4);
                #pragma unroll
                for (int m = 0; m < 8; ++m)
                    o2[m] = lds64(obase + (u32)(m * OP * 4) + (kof + k) * 4);
                #pragma unroll
                for (int m = 0; m < 8; ++m)
                    #pragma unroll
                    for (int j = 0; j < 6; ++j) fma2(acc[m][j], o2[m], w2[j]);
            }
        }

        const int wbid = ci / 5, t = ci % 5;
        const int b = wbid >> 6, widx = wbid & 63;
        const int hw = widx >> 3, ww = widx & 7;
        #pragma unroll
        for (int m = 0; m < 8; ++m) {
            const int mt = ty * 8 + m;
            const int hs = mt >> 3, wsv = mt & 7;
            const int h = (hw * 8 + hs + 4) & 63;
            const int w = (ww * 8 + wsv + 4) & 63;
            float* orow = out + ((size_t)((b * T_FRAMES + t) * 4096 + h * 64 + w)) * DIM;
            #pragma unroll
            for (int j = 0; j < 6; ++j) {
                float lo, hi; unpack2(acc[m][j], lo, hi);
                orow[j * 32 + tx] = lo + hi + pbv[j];
            }
        }
    }
}

// ---------------- launch ----------------
extern "C" void kernel_launch(void* const* d_in, const int* in_sizes, int n_in,
                              void* d_out, int out_size)
{
    const float* qkv        = (const float*)d_in[0];
    const float* bias_table = (const float*)d_in[1];
    const float* pw         = (const float*)d_in[2];
    const float* pb         = (const float*)d_in[3];
    float* out = (float*)d_out;

    int B = in_sizes[0] / (T_FRAMES * 64 * 64 * 3 * DIM);
    if (B < 1) B = 1;
    if (B > 2) B = 2;   // scratch sized for B=2 (problem fixed at B=2)

    cudaFuncSetAttribute(attn_kernel, cudaFuncAttributeMaxDynamicSharedMemorySize, ATTN_SMEM);
    cudaFuncSetAttribute(proj_kernel, cudaFuncAttributeMaxDynamicSharedMemorySize, PROJ_SMEM);

    dim3 ag(B * 64, HEADS);
    attn_kernel<<<ag, NTOK, ATTN_SMEM>>>(qkv, bias_table);

    const int nchunks = B * 64 * T_FRAMES;
    int pgrid = nchunks < 296 ? nchunks : 296;
    proj_kernel<<<pgrid, 256, PROJ_SMEM>>>(pw, pb, out, nchunks);
}

// round 3
// speedup vs baseline: 1.1043x; 1.1043x over previous
#include <cuda_runtime.h>

typedef unsigned long long u64;
typedef unsigned int u32;

#define T_FRAMES 5
#define WS 8
#define HEADS 6
#define DIM 192
#define HDIM 32
#define NTOK 320
#define KROW 36   // padded row (floats) for K/V smem tiles

// scratch: per-window attention output, [wb][n][DIM], sized for B=2
__device__ float g_scratch[2 * 64 * NTOK * DIM];

// ---------------- f32x2 helpers (sm_100+ packed fp32) ----------------
__device__ __forceinline__ u64 pack2(float lo, float hi) {
    u64 r; asm("mov.b64 %0,{%1,%2};" : "=l"(r) : "f"(lo), "f"(hi)); return r;
}
__device__ __forceinline__ void unpack2(u64 v, float &lo, float &hi) {
    asm("mov.b64 {%0,%1},%2;" : "=f"(lo), "=f"(hi) : "l"(v));
}
__device__ __forceinline__ u64 add2(u64 a, u64 b) {
    u64 r; asm("add.rn.f32x2 %0,%1,%2;" : "=l"(r) : "l"(a), "l"(b)); return r;
}
__device__ __forceinline__ void fma2(u64 &d, u64 a, u64 b) {
    asm("fma.rn.f32x2 %0,%1,%2,%0;" : "+l"(d) : "l"(a), "l"(b));
}
// 16B smem load, NON-volatile (memory clobber: ordered vs __syncthreads,
// but FMAs schedule freely around it; loads stay batched where written).
__device__ __forceinline__ void lds2(u64 &a, u64 &b, u32 sa) {
    asm("ld.shared.v2.b64 {%0,%1},[%2];" : "=l"(a), "=l"(b) : "r"(sa) : "memory");
}
__device__ __forceinline__ u64 lds64(u32 sa) {
    u64 r; asm("ld.shared.b64 %0,[%1];" : "=l"(r) : "r"(sa) : "memory"); return r;
}

// ---------------- attention kernel ----------------
// smem layout (floats): K tile | V tile | bias column | token meta
#define SM_V    (NTOK * KROW)
#define SM_BIAS (2 * NTOK * KROW)
#define SM_META (SM_BIAS + 1185)
#define ATTN_SMEM ((SM_META + NTOK) * 4)

__global__ void __launch_bounds__(320)
attn_kernel(const float* __restrict__ qkv, const float* __restrict__ bias_table)
{
    extern __shared__ float sm[];
    float* k_s    = sm;
    float* v_s    = sm + SM_V;
    float* bias_s = sm + SM_BIAS;
    int*   meta_s = (int*)(sm + SM_META);

    const int head = blockIdx.y;
    const int wb   = blockIdx.x;          // b*64 + widx
    const int b    = wb >> 6;
    const int widx = wb & 63;
    const int hw = widx >> 3, ww = widx & 7;

    const int i  = threadIdx.x;           // query token 0..319
    const int t  = i >> 6;
    const int hs = (i >> 3) & 7;
    const int wsv = i & 7;
    const int Hp = hw * 8 + hs;           // shifted-frame coords
    const int Wp = ww * 8 + wsv;
    const int h = (Hp + 4) & 63;          // un-shift: roll(-4) gather
    const int w = (Wp + 4) & 63;
    // Swin shift mask regions (computed, not loaded)
    const int rh = (Hp < 56) ? 0 : ((Hp < 60) ? 1 : 2);
    const int rw = (Wp < 56) ? 0 : ((Wp < 60) ? 1 : 2);
    const int r_i = rh * 3 + rw;
    const int bj  = t * 15 + hs + wsv;    // rel-bias component
    meta_s[i] = bj | (r_i << 8);

    const int row = ((b * T_FRAMES + t) << 12) + (h << 6) + w;
    const float* qp = qkv + (size_t)row * (3 * DIM) + head * HDIM;

    // K, V rows into smem — cooperative, coalesced: 16 consecutive threads
    // stage one token row (8 K float4s + 8 V float4s).
    {
        const int bT = b * T_FRAMES;
        #pragma unroll
        for (int it = 0; it < 16; ++it) {
            const int lin = it * NTOK + i;     // 0..5119
            const int r   = lin >> 4;
            const int g   = lin & 15;
            const int rt  = r >> 6;
            const int rhs = (r >> 3) & 7;
            const int rws = r & 7;
            const int rh_ = (hw * 8 + rhs + 4) & 63;
            const int rw_ = (ww * 8 + rws + 4) & 63;
            const float* rowp = qkv + (size_t)(((bT + rt) << 12) + (rh_ << 6) + rw_) * (3 * DIM)
                                + head * HDIM;
            const int gg = g & 7;
            const float4 val = ((const float4*)(rowp + DIM + ((g >= 8) ? DIM : 0)))[gg];
            float* dst = ((g >= 8) ? v_s : k_s) + r * KROW;
            ((float4*)dst)[gg] = val;
        }
    }
    const float LOG2E = 1.4426950408889634f;
    for (int idx = i; idx < 1185; idx += NTOK)
        bias_s[idx] = bias_table[idx * HEADS + head] * LOG2E;

    // q into registers, pre-scaled by SCALE * log2(e)
    const float qs_f = 0.17677669529663687f * LOG2E;
    u64 q[16];
    {
        const float4* qv = (const float4*)qp;
        #pragma unroll
        for (int m = 0; m < 8; ++m) {
            float4 f = qv[m];
            q[2 * m]     = pack2(f.x * qs_f, f.y * qs_f);
            q[2 * m + 1] = pack2(f.z * qs_f, f.w * qs_f);
        }
    }
    __syncthreads();

    const u32 kbase = (u32)__cvta_generic_to_shared(k_s);

    u64 acc[16];
    #pragma unroll
    for (int m = 0; m < 16; ++m) acc[m] = 0ULL;
    float l = 0.f;
    const int a_i = bj + 112;

    #pragma unroll 1
    for (int j = 0; j < NTOK; ++j) {
        const u32 ka = kbase + j * (KROW * 4);
        const u32 va = ka + SM_V * 4;
        // --- batched loads: full K row, then full V row (independent) ---
        u64 kr[16], vr[16];
        lds2(kr[0],  kr[1],  ka);
        lds2(kr[2],  kr[3],  ka + 16);
        lds2(kr[4],  kr[5],  ka + 32);
        lds2(kr[6],  kr[7],  ka + 48);
        lds2(kr[8],  kr[9],  ka + 64);
        lds2(kr[10], kr[11], ka + 80);
        lds2(kr[12], kr[13], ka + 96);
        lds2(kr[14], kr[15], ka + 112);
        lds2(vr[0],  vr[1],  va);
        lds2(vr[2],  vr[3],  va + 16);
        lds2(vr[4],  vr[5],  va + 32);
        lds2(vr[6],  vr[7],  va + 48);
        lds2(vr[8],  vr[9],  va + 64);
        lds2(vr[10], vr[11], va + 80);
        lds2(vr[12], vr[13], va + 96);
        lds2(vr[14], vr[15], va + 112);
        const int mj = meta_s[j];
        // --- dot product: 16 independent fma2 into 4 chains ---
        u64 d0 = 0, d1 = 0, d2 = 0, d3 = 0;
        fma2(d0, q[0],  kr[0]);  fma2(d1, q[1],  kr[1]);
        fma2(d2, q[2],  kr[2]);  fma2(d3, q[3],  kr[3]);
        fma2(d0, q[4],  kr[4]);  fma2(d1, q[5],  kr[5]);
        fma2(d2, q[6],  kr[6]);  fma2(d3, q[7],  kr[7]);
        fma2(d0, q[8],  kr[8]);  fma2(d1, q[9],  kr[9]);
        fma2(d2, q[10], kr[10]); fma2(d3, q[11], kr[11]);
        fma2(d0, q[12], kr[12]); fma2(d1, q[13], kr[13]);
        fma2(d2, q[14], kr[14]); fma2(d3, q[15], kr[15]);
        u64 e = add2(add2(d0, d1), add2(d2, d3));
        float sx, sy; unpack2(e, sx, sy);
        const float s = sx + sy + bias_s[a_i - (mj & 255)];
        float p; asm("ex2.approx.ftz.f32 %0,%1;" : "=f"(p) : "f"(s));
        p = ((mj >> 8) == r_i) ? p : 0.f;   // mask: exclude cross-region keys
        l += p;
        const u64 pp = pack2(p, p);
        fma2(acc[0],  vr[0],  pp); fma2(acc[1],  vr[1],  pp);
        fma2(acc[2],  vr[2],  pp); fma2(acc[3],  vr[3],  pp);
        fma2(acc[4],  vr[4],  pp); fma2(acc[5],  vr[5],  pp);
        fma2(acc[6],  vr[6],  pp); fma2(acc[7],  vr[7],  pp);
        fma2(acc[8],  vr[8],  pp); fma2(acc[9],  vr[9],  pp);
        fma2(acc[10], vr[10], pp); fma2(acc[11], vr[11], pp);
        fma2(acc[12], vr[12], pp); fma2(acc[13], vr[13], pp);
        fma2(acc[14], vr[14], pp); fma2(acc[15], vr[15], pp);
    }

    const float inv = 1.0f / l;
    float4* op = (float4*)(g_scratch + ((size_t)(wb * NTOK + i)) * DIM + head * HDIM);
    #pragma unroll
    for (int m = 0; m < 8; ++m) {
        float x0, x1, x2, x3;
        unpack2(acc[2 * m],     x0, x1);
        unpack2(acc[2 * m + 1], x2, x3);
        op[m] = make_float4(x0 * inv, x1 * inv, x2 * inv, x3 * inv);
    }
}

// ---------------- projection + window-reverse kernel ----------------
// 384 threads (12 warps). Warp w owns output channels [w*16, w*16+16).
// W staged ONCE per persistent CTA: [192][WPAD] c-major. W reads are
// warp-uniform broadcasts; o reads lane-strided conflict-free (194 words).
#define WPAD 194
#define PROJ_SMEM ((DIM * WPAD + 64 * WPAD) * 4)

__global__ void __launch_bounds__(384)
proj_kernel(const float* __restrict__ pw, const float* __restrict__ pb,
            float* __restrict__ out, int nchunks)
{
    extern __shared__ float sm[];
    float* Wsh = sm;                 // [192][WPAD]
    float* o_s = sm + DIM * WPAD;    // [64][WPAD]
    const int tid = threadIdx.x, tx = tid & 31, wid = tid >> 5;
    const int c0 = wid * 16;

    // stage full W once (float2, coalesced)
    for (int idx = tid; idx < DIM * 96; idx += 384) {
        const int c = idx / 96, kk = idx % 96;
        float2 v = *(const float2*)(pw + c * DIM + kk * 2);
        *(float2*)(Wsh + c * WPAD + kk * 2) = v;
    }
    float pbv[16];
    #pragma unroll
    for (int j = 0; j < 16; ++j) pbv[j] = pb[c0 + j];

    const u32 wbase = (u32)__cvta_generic_to_shared(Wsh) + c0 * (WPAD * 4);
    const u32 obase = (u32)__cvta_generic_to_shared(o_s) + tx * (WPAD * 4);

    for (int ci = blockIdx.x; ci < nchunks; ci += gridDim.x) {
        __syncthreads();   // W staged (first iter) / previous chunk consumed
        // stage o chunk [64 tokens][192 k] as float2
        const float* src = g_scratch + (size_t)ci * (64 * DIM);  // ci = wb*5 + t
        #pragma unroll
        for (int it = 0; it < 16; ++it) {
            const int idx = tid + it * 384;
            const int tok = idx / 96, kk = idx % 96;
            float2 v = *(const float2*)(src + tok * DIM + kk * 2);
            *(float2*)(o_s + tok * WPAD + kk * 2) = v;
        }
        __syncthreads();

        u64 acc0[16], acc1[16];
        #pragma unroll
        for (int j = 0; j < 16; ++j) { acc0[j] = 0ULL; acc1[j] = 0ULL; }

        #pragma unroll 1
        for (int k2 = 0; k2 < 96; ++k2) {
            u64 w2[16];
            #pragma unroll
            for (int j = 0; j < 16; ++j)
                w2[j] = lds64(wbase + (u32)(j * WPAD * 4) + k2 * 8);  // broadcast
            const u64 o0 = lds64(obase + k2 * 8);
            const u64 o1 = lds64(obase + 32 * (WPAD * 4) + k2 * 8);
            #pragma unroll
            for (int j = 0; j < 16; ++j) fma2(acc0[j], o0, w2[j]);
            #pragma unroll
            for (int j = 0; j < 16; ++j) fma2(acc1[j], o1, w2[j]);
        }

        const int wbid = ci / 5, t = ci % 5;
        const int b = wbid >> 6, widx = wbid & 63;
        const int hw = widx >> 3, ww = widx & 7;
        #pragma unroll
        for (int half = 0; half < 2; ++half) {
            const int tok = tx + half * 32;
            const int hs = tok >> 3, wsv = tok & 7;
            const int h = (hw * 8 + hs + 4) & 63;
            const int w = (ww * 8 + wsv + 4) & 63;
            float* orow = out + ((size_t)((b * T_FRAMES + t) * 4096 + h * 64 + w)) * DIM + c0;
            const u64* a = half ? acc1 : acc0;
            #pragma unroll
            for (int f4 = 0; f4 < 4; ++f4) {
                float r[4];
                #pragma unroll
                for (int e = 0; e < 4; ++e) {
                    float lo, hi; unpack2(a[f4 * 4 + e], lo, hi);
                    r[e] = lo + hi + pbv[f4 * 4 + e];
                }
                *(float4*)(orow + f4 * 4) = make_float4(r[0], r[1], r[2], r[3]);
            }
        }
    }
}

// ---------------- launch ----------------
extern "C" void kernel_launch(void* const* d_in, const int* in_sizes, int n_in,
                              void* d_out, int out_size)
{
    const float* qkv        = (const float*)d_in[0];
    const float* bias_table = (const float*)d_in[1];
    const float* pw         = (const float*)d_in[2];
    const float* pb         = (const float*)d_in[3];
    float* out = (float*)d_out;

    int B = in_sizes[0] / (T_FRAMES * 64 * 64 * 3 * DIM);
    if (B < 1) B = 1;
    if (B > 2) B = 2;   // scratch sized for B=2 (problem fixed at B=2)

    cudaFuncSetAttribute(attn_kernel, cudaFuncAttributeMaxDynamicSharedMemorySize, ATTN_SMEM);
    cudaFuncSetAttribute(proj_kernel, cudaFuncAttributeMaxDynamicSharedMemorySize, PROJ_SMEM);

    dim3 ag(B * 64, HEADS);
    attn_kernel<<<ag, NTOK, ATTN_SMEM>>>(qkv, bias_table);

    const int nchunks = B * 64 * T_FRAMES;
    int pgrid = nchunks < 148 ? nchunks : 148;
    proj_kernel<<<pgrid, 384, PROJ_SMEM>>>(pw, pb, out, nchunks);
}